// round 3
// baseline (speedup 1.0000x reference)
#include <cuda_runtime.h>
#include <math.h>

// ---------------------------------------------------------------------------
// Problem constants
// ---------------------------------------------------------------------------
#define BATCH 64
#define GRID_N 32
#define TOK 1024          // GRID_N*GRID_N
#define HID 1024

// Expert configs: (img, patch, grid, channels, K=3*p*p, Kpad)
// E0: 448,14,32,1024, K=588, Kp=592
// E1: 336,14,24, 768, K=588, Kp=592
// E2: 448,32,14,1152, K=3072, Kp=3072

// ---------------------------------------------------------------------------
// Scratch (device globals -- no allocation allowed)
// ---------------------------------------------------------------------------
__device__ float g_x336[BATCH * 3 * 336 * 336];          //  86.7 MB
__device__ float g_patches[BATCH * 1024 * 592];          // 155.2 MB (max of all 3)
__device__ float g_feat[BATCH * 1024 * 1024];            // 268.4 MB (tower out max)
__device__ float g_feat2[BATCH * 1024 * 1152];           // 302.0 MB (resized feat max)
__device__ float g_wi[3 * BATCH];

// ---------------------------------------------------------------------------
// Routing weights: w_i[b] = sum_k (selected[b,k]==i) * rw[b,k]
// ---------------------------------------------------------------------------
__global__ void wi_kernel(const int* __restrict__ sel,
                          const float* __restrict__ rw) {
    int b = threadIdx.x;
    if (b >= BATCH) return;
    float w0 = 0.f, w1 = 0.f, w2 = 0.f;
    #pragma unroll
    for (int k = 0; k < 2; k++) {
        int e = sel[b * 2 + k];
        float r = rw[b * 2 + k];
        if (e == 0) w0 += r;
        else if (e == 1) w1 += r;
        else w2 += r;
    }
    g_wi[0 * BATCH + b] = w0;
    g_wi[1 * BATCH + b] = w1;
    g_wi[2 * BATCH + b] = w2;
}

// ---------------------------------------------------------------------------
// Bilinear image resize 448 -> 336, align_corners=True
// ---------------------------------------------------------------------------
__global__ void resize_img_kernel(const float* __restrict__ x) {
    const int S = 336, H = 448;
    int idx = blockIdx.x * blockDim.x + threadIdx.x;
    const int total = BATCH * 3 * S * S;
    if (idx >= total) return;
    int ox = idx % S;
    int oy = (idx / S) % S;
    int bc = idx / (S * S);

    float fy = (float)oy * ((float)(H - 1) / (float)(S - 1));
    float fx = (float)ox * ((float)(H - 1) / (float)(S - 1));
    int y0 = (int)floorf(fy); y0 = min(max(y0, 0), H - 1);
    int x0 = (int)floorf(fx); x0 = min(max(x0, 0), H - 1);
    int y1 = min(y0 + 1, H - 1);
    int x1 = min(x0 + 1, H - 1);
    float ty = fy - (float)y0;
    float tx = fx - (float)x0;

    const float* p = x + (size_t)bc * H * H;
    float a = p[y0 * H + x0] * (1.f - ty) + p[y1 * H + x0] * ty;
    float b = p[y0 * H + x1] * (1.f - ty) + p[y1 * H + x1] * ty;
    g_x336[idx] = a * (1.f - tx) + b * tx;
}

// ---------------------------------------------------------------------------
// Patchify: src [B,3,s,s] -> g_patches [B, g*g, Kp] (K = 3*p*p, zero-padded)
// token t = gy*g+gx, feature kk = ch*p*p + py*p + px
// ---------------------------------------------------------------------------
__global__ void patchify_kernel(const float* __restrict__ src,
                                int s, int p, int g, int K, int Kp) {
    int idx = blockIdx.x * blockDim.x + threadIdx.x;
    int total = BATCH * g * g * Kp;
    if (idx >= total) return;
    int kk = idx % Kp;
    int t  = (idx / Kp) % (g * g);
    int b  = idx / (Kp * g * g);
    float v = 0.f;
    if (kk < K) {
        int pp = p * p;
        int ch = kk / pp;
        int r  = kk % pp;
        int py = r / p, px = r % p;
        int gy = t / g, gx = t % g;
        v = src[(((size_t)b * 3 + ch) * s + (gy * p + py)) * s + (gx * p + px)];
    }
    g_patches[idx] = v;
}

// ---------------------------------------------------------------------------
// Feature grid bilinear resize g x g -> 32 x 32 (align_corners), token-major.
// in:  g_feat  [B, g*g, c]   out: g_feat2 [B, 1024, c]
// ---------------------------------------------------------------------------
__global__ void resize_feat_kernel(int g, int c) {
    int idx = blockIdx.x * blockDim.x + threadIdx.x;
    int total = BATCH * TOK * c;
    if (idx >= total) return;
    int ch = idx % c;
    int t  = (idx / c) % TOK;
    int b  = idx / (c * TOK);
    int ty = t / GRID_N, tx = t % GRID_N;

    float fy = (float)ty * ((float)(g - 1) / (float)(GRID_N - 1));
    float fx = (float)tx * ((float)(g - 1) / (float)(GRID_N - 1));
    int y0 = (int)floorf(fy); y0 = min(max(y0, 0), g - 1);
    int x0 = (int)floorf(fx); x0 = min(max(x0, 0), g - 1);
    int y1 = min(y0 + 1, g - 1);
    int x1 = min(x0 + 1, g - 1);
    float dy = fy - (float)y0;
    float dx = fx - (float)x0;

    const float* fb = g_feat + (size_t)b * g * g * c + ch;
    float v00 = fb[(size_t)(y0 * g + x0) * c];
    float v01 = fb[(size_t)(y0 * g + x1) * c];
    float v10 = fb[(size_t)(y1 * g + x0) * c];
    float v11 = fb[(size_t)(y1 * g + x1) * c];
    g_feat2[idx] = (v00 * (1.f - dy) + v10 * dy) * (1.f - dx)
                 + (v01 * (1.f - dy) + v11 * dy) * dx;
}

// ---------------------------------------------------------------------------
// Classic 128x128x8 SGEMM, 256 threads, 8x8 register tile per thread.
// C[M,N] = A[M,K(lda)] * W[K,N(ldb)] + bias;  optional per-sample scale and +=.
// Requirements (all satisfied by this problem):
//   M % 128 == 0, N % 128 == 0, A readable up to (K+7)&~7 per row (zero-padded
//   when lda > K), base pointers 16B aligned, lda/ldb/ldc multiples of 4.
// rowscale: per-sample scale (1024 tokens/sample), nullptr -> 1.0
// ---------------------------------------------------------------------------
__global__ __launch_bounds__(256)
void sgemm_kernel(const float* __restrict__ A, int lda,
                  const float* __restrict__ W, int ldb, int K,
                  const float* __restrict__ bias,
                  float* __restrict__ C, int ldc,
                  const float* __restrict__ rowscale,
                  int accumulate) {
    __shared__ float As[8][128];
    __shared__ float Bs[8][128];

    const int tid  = threadIdx.x;
    const int row0 = blockIdx.y * 128;
    const int col0 = blockIdx.x * 128;

    // A loader: 2 threads per row, float4 each (128 rows x 8 cols)
    const int a_row = tid >> 1;
    const int a_col = (tid & 1) * 4;
    // B loader: 32 threads per row, float4 each (8 rows x 128 cols)
    const int b_row = tid >> 5;
    const int b_col = (tid & 31) * 4;

    const float* Aptr = A + (size_t)(row0 + a_row) * lda + a_col;
    const float* Bptr = W + (size_t)b_row * ldb + col0 + b_col;

    const int tx = (tid & 15) * 8;   // col offset of 8x8 tile
    const int ty = (tid >> 4) * 8;   // row offset of 8x8 tile

    float acc[8][8];
    #pragma unroll
    for (int i = 0; i < 8; i++)
        #pragma unroll
        for (int j = 0; j < 8; j++) acc[i][j] = 0.f;

    const int Kp = (K + 7) & ~7;
    for (int k0 = 0; k0 < Kp; k0 += 8) {
        float4 av = *(const float4*)(Aptr + k0);
        As[a_col + 0][a_row] = av.x;
        As[a_col + 1][a_row] = av.y;
        As[a_col + 2][a_row] = av.z;
        As[a_col + 3][a_row] = av.w;

        float4 bv;
        if (k0 + b_row < K) bv = *(const float4*)(Bptr + (size_t)k0 * ldb);
        else                bv = make_float4(0.f, 0.f, 0.f, 0.f);
        *(float4*)&Bs[b_row][b_col] = bv;

        __syncthreads();

        #pragma unroll
        for (int kk = 0; kk < 8; kk++) {
            float ar[8], br[8];
            *(float4*)(ar)     = *(const float4*)&As[kk][ty];
            *(float4*)(ar + 4) = *(const float4*)&As[kk][ty + 4];
            *(float4*)(br)     = *(const float4*)&Bs[kk][tx];
            *(float4*)(br + 4) = *(const float4*)&Bs[kk][tx + 4];
            #pragma unroll
            for (int i = 0; i < 8; i++)
                #pragma unroll
                for (int j = 0; j < 8; j++)
                    acc[i][j] = fmaf(ar[i], br[j], acc[i][j]);
        }
        __syncthreads();
    }

    // Epilogue. For projector GEMMs the 128-row block lies inside one sample
    // (1024 tokens/sample, row0 % 128 == 0, 1024 % 128 == 0).
    float scale = 1.f;
    if (rowscale) scale = rowscale[row0 >> 10];

    float4 bias_lo = *(const float4*)(bias + col0 + tx);
    float4 bias_hi = *(const float4*)(bias + col0 + tx + 4);

    #pragma unroll
    for (int i = 0; i < 8; i++) {
        float* crow = C + (size_t)(row0 + ty + i) * ldc + col0 + tx;
        float4 v0, v1;
        v0.x = (acc[i][0] + bias_lo.x) * scale;
        v0.y = (acc[i][1] + bias_lo.y) * scale;
        v0.z = (acc[i][2] + bias_lo.z) * scale;
        v0.w = (acc[i][3] + bias_lo.w) * scale;
        v1.x = (acc[i][4] + bias_hi.x) * scale;
        v1.y = (acc[i][5] + bias_hi.y) * scale;
        v1.z = (acc[i][6] + bias_hi.z) * scale;
        v1.w = (acc[i][7] + bias_hi.w) * scale;
        if (accumulate) {
            float4 o0 = *(float4*)(crow);
            float4 o1 = *(float4*)(crow + 4);
            v0.x += o0.x; v0.y += o0.y; v0.z += o0.z; v0.w += o0.w;
            v1.x += o1.x; v1.y += o1.y; v1.z += o1.z; v1.w += o1.w;
        }
        *(float4*)(crow)     = v0;
        *(float4*)(crow + 4) = v1;
    }
}

// ---------------------------------------------------------------------------
// Launch
// ---------------------------------------------------------------------------
extern "C" void kernel_launch(void* const* d_in, const int* in_sizes, int n_in,
                              void* d_out, int out_size) {
    const float* x   = (const float*)d_in[0];
    const int*   sel = (const int*)d_in[1];
    const float* rw  = (const float*)d_in[2];
    const float* wt[3] = {(const float*)d_in[3],  (const float*)d_in[7],  (const float*)d_in[11]};
    const float* bt[3] = {(const float*)d_in[4],  (const float*)d_in[8],  (const float*)d_in[12]};
    const float* wp[3] = {(const float*)d_in[5],  (const float*)d_in[9],  (const float*)d_in[13]};
    const float* bp[3] = {(const float*)d_in[6],  (const float*)d_in[10], (const float*)d_in[14]};
    float* out = (float*)d_out;

    float *p_x336, *p_patches, *p_feat, *p_feat2, *p_wi;
    cudaGetSymbolAddress((void**)&p_x336,    g_x336);
    cudaGetSymbolAddress((void**)&p_patches, g_patches);
    cudaGetSymbolAddress((void**)&p_feat,    g_feat);
    cudaGetSymbolAddress((void**)&p_feat2,   g_feat2);
    cudaGetSymbolAddress((void**)&p_wi,      g_wi);

    const int T = 256;
    wi_kernel<<<1, 64>>>(sel, rw);

    // ---------------- Expert 0: s=448, p=14, g=32, c=1024 (no resizes) -----
    {
        int g = 32, K = 588, Kp = 592, c = 1024;
        int ptotal = BATCH * g * g * Kp;
        patchify_kernel<<<(ptotal + T - 1) / T, T>>>(x, 448, 14, g, K, Kp);
        // tower: [65536 x 588] @ [588 x 1024]
        sgemm_kernel<<<dim3(c / 128, BATCH * g * g / 128), 256>>>(
            p_patches, Kp, wt[0], c, K, bt[0], p_feat, c, nullptr, 0);
        // proj: [65536 x 1024] @ [1024 x 1024]  (writes out, scaled)
        sgemm_kernel<<<dim3(HID / 128, BATCH * TOK / 128), 256>>>(
            p_feat, c, wp[0], HID, c, bp[0], out, HID, p_wi + 0 * BATCH, 0);
    }

    // ---------------- Expert 1: s=336, p=14, g=24, c=768 -------------------
    {
        int g = 24, K = 588, Kp = 592, c = 768;
        int rtotal = BATCH * 3 * 336 * 336;
        resize_img_kernel<<<(rtotal + T - 1) / T, T>>>(x);
        int ptotal = BATCH * g * g * Kp;
        patchify_kernel<<<(ptotal + T - 1) / T, T>>>(p_x336, 336, 14, g, K, Kp);
        // tower: [36864 x 588] @ [588 x 768]
        sgemm_kernel<<<dim3(c / 128, BATCH * g * g / 128), 256>>>(
            p_patches, Kp, wt[1], c, K, bt[1], p_feat, c, nullptr, 0);
        int ftotal = BATCH * TOK * c;
        resize_feat_kernel<<<(ftotal + T - 1) / T, T>>>(g, c);
        // proj: [65536 x 768] @ [768 x 1024]  (accumulate)
        sgemm_kernel<<<dim3(HID / 128, BATCH * TOK / 128), 256>>>(
            p_feat2, c, wp[1], HID, c, bp[1], out, HID, p_wi + 1 * BATCH, 1);
    }

    // ---------------- Expert 2: s=448, p=32, g=14, c=1152 ------------------
    {
        int g = 14, K = 3072, Kp = 3072, c = 1152;
        int ptotal = BATCH * g * g * Kp;
        patchify_kernel<<<(ptotal + T - 1) / T, T>>>(x, 448, 32, g, K, Kp);
        // tower: [12544 x 3072] @ [3072 x 1152]
        sgemm_kernel<<<dim3(c / 128, BATCH * g * g / 128), 256>>>(
            p_patches, Kp, wt[2], c, K, bt[2], p_feat, c, nullptr, 0);
        int ftotal = BATCH * TOK * c;
        resize_feat_kernel<<<(ftotal + T - 1) / T, T>>>(g, c);
        // proj: [65536 x 1152] @ [1152 x 1024] (accumulate)
        sgemm_kernel<<<dim3(HID / 128, BATCH * TOK / 128), 256>>>(
            p_feat2, c, wp[2], HID, c, bp[2], out, HID, p_wi + 2 * BATCH, 1);
    }
}

// round 6
// speedup vs baseline: 2.1602x; 2.1602x over previous
#include <cuda_runtime.h>
#include <math.h>
#include <stdint.h>

// ---------------------------------------------------------------------------
// Problem constants
// ---------------------------------------------------------------------------
#define BATCH 64
#define GRID_N 32
#define TOK 1024          // GRID_N*GRID_N
#define HID 1024

// Expert configs: (img, patch, grid, channels, K=3*p*p, Kpad)
// E0: 448,14,32,1024, K=588, Kp=592
// E1: 336,14,24, 768, K=588, Kp=592
// E2: 448,32,14,1152, K=3072

// ---------------------------------------------------------------------------
// Scratch (device globals -- no allocation allowed)
// ---------------------------------------------------------------------------
__device__ float g_x336[BATCH * 3 * 336 * 336];
__device__ float g_patches[BATCH * 1024 * 592];
__device__ float g_feat[BATCH * 1024 * 1024];
__device__ float g_feat2[BATCH * 1024 * 1152];
__device__ float g_wi[3 * BATCH];

// ---------------------------------------------------------------------------
// Routing weights
// ---------------------------------------------------------------------------
__global__ void wi_kernel(const int* __restrict__ sel,
                          const float* __restrict__ rw) {
    int b = threadIdx.x;
    if (b >= BATCH) return;
    float w0 = 0.f, w1 = 0.f, w2 = 0.f;
    #pragma unroll
    for (int k = 0; k < 2; k++) {
        int e = sel[b * 2 + k];
        float r = rw[b * 2 + k];
        if (e == 0) w0 += r;
        else if (e == 1) w1 += r;
        else w2 += r;
    }
    g_wi[0 * BATCH + b] = w0;
    g_wi[1 * BATCH + b] = w1;
    g_wi[2 * BATCH + b] = w2;
}

// ---------------------------------------------------------------------------
// Bilinear image resize 448 -> 336, align_corners=True
// ---------------------------------------------------------------------------
__global__ void resize_img_kernel(const float* __restrict__ x) {
    const int S = 336, H = 448;
    int idx = blockIdx.x * blockDim.x + threadIdx.x;
    const int total = BATCH * 3 * S * S;
    if (idx >= total) return;
    int ox = idx % S;
    int oy = (idx / S) % S;
    int bc = idx / (S * S);

    float fy = (float)oy * ((float)(H - 1) / (float)(S - 1));
    float fx = (float)ox * ((float)(H - 1) / (float)(S - 1));
    int y0 = (int)floorf(fy); y0 = min(max(y0, 0), H - 1);
    int x0 = (int)floorf(fx); x0 = min(max(x0, 0), H - 1);
    int y1 = min(y0 + 1, H - 1);
    int x1 = min(x0 + 1, H - 1);
    float ty = fy - (float)y0;
    float tx = fx - (float)x0;

    const float* p = x + (size_t)bc * H * H;
    float a = p[y0 * H + x0] * (1.f - ty) + p[y1 * H + x0] * ty;
    float b = p[y0 * H + x1] * (1.f - ty) + p[y1 * H + x1] * ty;
    g_x336[idx] = a * (1.f - tx) + b * tx;
}

// ---------------------------------------------------------------------------
// Patchify: src [B,3,s,s] -> g_patches [B, g*g, Kp] (K = 3*p*p, zero-padded)
// ---------------------------------------------------------------------------
__global__ void patchify_kernel(const float* __restrict__ src,
                                int s, int p, int g, int K, int Kp) {
    int idx = blockIdx.x * blockDim.x + threadIdx.x;
    int total = BATCH * g * g * Kp;
    if (idx >= total) return;
    int kk = idx % Kp;
    int t  = (idx / Kp) % (g * g);
    int b  = idx / (Kp * g * g);
    float v = 0.f;
    if (kk < K) {
        int pp = p * p;
        int ch = kk / pp;
        int r  = kk % pp;
        int py = r / p, px = r % p;
        int gy = t / g, gx = t % g;
        v = src[(((size_t)b * 3 + ch) * s + (gy * p + py)) * s + (gx * p + px)];
    }
    g_patches[idx] = v;
}

// ---------------------------------------------------------------------------
// Feature grid bilinear resize g x g -> 32 x 32
// ---------------------------------------------------------------------------
__global__ void resize_feat_kernel(int g, int c) {
    int idx = blockIdx.x * blockDim.x + threadIdx.x;
    int total = BATCH * TOK * c;
    if (idx >= total) return;
    int ch = idx % c;
    int t  = (idx / c) % TOK;
    int b  = idx / (c * TOK);
    int ty = t / GRID_N, tx = t % GRID_N;

    float fy = (float)ty * ((float)(g - 1) / (float)(GRID_N - 1));
    float fx = (float)tx * ((float)(g - 1) / (float)(GRID_N - 1));
    int y0 = (int)floorf(fy); y0 = min(max(y0, 0), g - 1);
    int x0 = (int)floorf(fx); x0 = min(max(x0, 0), g - 1);
    int y1 = min(y0 + 1, g - 1);
    int x1 = min(x0 + 1, g - 1);
    float dy = fy - (float)y0;
    float dx = fx - (float)x0;

    const float* fb = g_feat + (size_t)b * g * g * c + ch;
    float v00 = fb[(size_t)(y0 * g + x0) * c];
    float v01 = fb[(size_t)(y0 * g + x1) * c];
    float v10 = fb[(size_t)(y1 * g + x0) * c];
    float v11 = fb[(size_t)(y1 * g + x1) * c];
    g_feat2[idx] = (v00 * (1.f - dy) + v10 * dy) * (1.f - dx)
                 + (v01 * (1.f - dy) + v11 * dy) * dx;
}

// ---------------------------------------------------------------------------
// TF32 tensor-core GEMM: C[M,N] = A[M,K] * W[K,N] + bias, optional scale/acc.
//   Tile 128x128x32, 256 threads, 8 warps of 64x32 (4x4 frags of m16n8k8).
//   Smem k-major with stride 136 -> conflict-free fragment LDS.
// Requirements: M%128==0, N%128==0, lda/ldb/ldc mult of 4, base 16B aligned,
//   A rows zero-padded & readable on [K, lda) when lda > K.
// ---------------------------------------------------------------------------
#define BK 32
#define SSTR 136

__device__ __forceinline__ uint32_t f2tf32(float x) {
    uint32_t r;
    asm("cvt.rna.tf32.f32 %0, %1;" : "=r"(r) : "f"(x));
    return r;
}

__device__ __forceinline__ void mma_tf32(float* d, const uint32_t* a, const uint32_t* b) {
    asm volatile(
        "mma.sync.aligned.m16n8k8.row.col.f32.tf32.tf32.f32 "
        "{%0,%1,%2,%3}, {%4,%5,%6,%7}, {%8,%9}, {%0,%1,%2,%3};\n"
        : "+f"(d[0]), "+f"(d[1]), "+f"(d[2]), "+f"(d[3])
        : "r"(a[0]), "r"(a[1]), "r"(a[2]), "r"(a[3]),
          "r"(b[0]), "r"(b[1]));
}

__global__ __launch_bounds__(256, 2)
void tf32_gemm_kernel(const float* __restrict__ A, int lda,
                      const float* __restrict__ W, int ldb, int K,
                      const float* __restrict__ bias,
                      float* __restrict__ C, int ldc,
                      const float* __restrict__ rowscale,
                      int accumulate) {
    __shared__ uint32_t As[BK][SSTR];   // k-major: As[k][m]
    __shared__ uint32_t Bs[BK][SSTR];   // k-major: Bs[k][n]

    const int tid  = threadIdx.x;
    const int lane = tid & 31;
    const int warp = tid >> 5;
    const int wm   = warp & 1;      // 0..1  -> 64-row slab
    const int wn   = warp >> 1;     // 0..3  -> 32-col slab
    const int g    = lane >> 2;     // groupID   0..7
    const int c    = lane & 3;      // tid_in_group 0..3

    const int row0 = blockIdx.y * 128;
    const int col0 = blockIdx.x * 128;

    float acc[4][4][4];
    #pragma unroll
    for (int i = 0; i < 4; i++)
        #pragma unroll
        for (int j = 0; j < 4; j++)
            #pragma unroll
            for (int r = 0; r < 4; r++) acc[i][j][r] = 0.f;

    const int KP = (K + 31) & ~31;

    for (int k0 = 0; k0 < KP; k0 += BK) {
        // ---- gmem -> regs ----
        // A: 128 rows x 32 cols = 1024 float4 slots, 4 per thread
        float4 av[4];
        int arow[4], acg[4];
        #pragma unroll
        for (int it = 0; it < 4; it++) {
            int slot = tid + 256 * it;
            arow[it] = slot >> 3;             // 0..127
            acg[it]  = (slot & 7) * 4;        // 0..28
            int kk = k0 + acg[it];
            if (kk < lda)
                av[it] = *(const float4*)(A + (size_t)(row0 + arow[it]) * lda + kk);
            else
                av[it] = make_float4(0.f, 0.f, 0.f, 0.f);
        }
        // B: 32 rows x 128 cols = 1024 float4 slots, 4 per thread
        float4 bv[4];
        int brow[4], bnc[4];
        #pragma unroll
        for (int it = 0; it < 4; it++) {
            int slot = tid + 256 * it;
            brow[it] = slot >> 5;             // 0..31
            bnc[it]  = (slot & 31) * 4;       // 0..124
            int kk = k0 + brow[it];
            if (kk < K)
                bv[it] = *(const float4*)(W + (size_t)kk * ldb + col0 + bnc[it]);
            else
                bv[it] = make_float4(0.f, 0.f, 0.f, 0.f);
        }

        __syncthreads();   // previous tile fully consumed

        // ---- regs -> smem (convert to tf32) ----
        #pragma unroll
        for (int it = 0; it < 4; it++) {
            As[acg[it] + 0][arow[it]] = f2tf32(av[it].x);
            As[acg[it] + 1][arow[it]] = f2tf32(av[it].y);
            As[acg[it] + 2][arow[it]] = f2tf32(av[it].z);
            As[acg[it] + 3][arow[it]] = f2tf32(av[it].w);
        }
        #pragma unroll
        for (int it = 0; it < 4; it++) {
            uint4 t;
            t.x = f2tf32(bv[it].x);
            t.y = f2tf32(bv[it].y);
            t.z = f2tf32(bv[it].z);
            t.w = f2tf32(bv[it].w);
            *(uint4*)&Bs[brow[it]][bnc[it]] = t;
        }

        __syncthreads();

        // ---- compute: 4 k-steps of 8 ----
        #pragma unroll
        for (int ks = 0; ks < BK; ks += 8) {
            uint32_t af[4][4];
            uint32_t bf[4][2];
            #pragma unroll
            for (int mi = 0; mi < 4; mi++) {
                int row = wm * 64 + mi * 16 + g;
                af[mi][0] = As[ks + c    ][row];
                af[mi][1] = As[ks + c    ][row + 8];
                af[mi][2] = As[ks + c + 4][row];
                af[mi][3] = As[ks + c + 4][row + 8];
            }
            #pragma unroll
            for (int ni = 0; ni < 4; ni++) {
                int col = wn * 32 + ni * 8 + g;
                bf[ni][0] = Bs[ks + c    ][col];
                bf[ni][1] = Bs[ks + c + 4][col];
            }
            #pragma unroll
            for (int mi = 0; mi < 4; mi++)
                #pragma unroll
                for (int ni = 0; ni < 4; ni++)
                    mma_tf32(acc[mi][ni], af[mi], bf[ni]);
        }
        __syncthreads();
    }

    // ---- epilogue ----
    float scale = 1.f;
    if (rowscale) scale = rowscale[row0 >> 10];

    #pragma unroll
    for (int mi = 0; mi < 4; mi++) {
        int r0 = row0 + wm * 64 + mi * 16 + g;
        #pragma unroll
        for (int ni = 0; ni < 4; ni++) {
            int col = col0 + wn * 32 + ni * 8 + 2 * c;
            float b0 = bias[col], b1 = bias[col + 1];

            float2 v0, v1;
            v0.x = (acc[mi][ni][0] + b0) * scale;
            v0.y = (acc[mi][ni][1] + b1) * scale;
            v1.x = (acc[mi][ni][2] + b0) * scale;
            v1.y = (acc[mi][ni][3] + b1) * scale;

            float* p0 = C + (size_t)r0 * ldc + col;
            float* p1 = C + (size_t)(r0 + 8) * ldc + col;
            if (accumulate) {
                float2 o0 = *(float2*)p0;
                float2 o1 = *(float2*)p1;
                v0.x += o0.x; v0.y += o0.y;
                v1.x += o1.x; v1.y += o1.y;
            }
            *(float2*)p0 = v0;
            *(float2*)p1 = v1;
        }
    }
}

// ---------------------------------------------------------------------------
// Launch
// ---------------------------------------------------------------------------
extern "C" void kernel_launch(void* const* d_in, const int* in_sizes, int n_in,
                              void* d_out, int out_size) {
    const float* x   = (const float*)d_in[0];
    const int*   sel = (const int*)d_in[1];
    const float* rw  = (const float*)d_in[2];
    const float* wt[3] = {(const float*)d_in[3],  (const float*)d_in[7],  (const float*)d_in[11]};
    const float* bt[3] = {(const float*)d_in[4],  (const float*)d_in[8],  (const float*)d_in[12]};
    const float* wp[3] = {(const float*)d_in[5],  (const float*)d_in[9],  (const float*)d_in[13]};
    const float* bp[3] = {(const float*)d_in[6],  (const float*)d_in[10], (const float*)d_in[14]};
    float* out = (float*)d_out;

    float *p_x336, *p_patches, *p_feat, *p_feat2, *p_wi;
    cudaGetSymbolAddress((void**)&p_x336,    g_x336);
    cudaGetSymbolAddress((void**)&p_patches, g_patches);
    cudaGetSymbolAddress((void**)&p_feat,    g_feat);
    cudaGetSymbolAddress((void**)&p_feat2,   g_feat2);
    cudaGetSymbolAddress((void**)&p_wi,      g_wi);

    const int T = 256;
    wi_kernel<<<1, 64>>>(sel, rw);

    // ---------------- Expert 0: s=448, p=14, g=32, c=1024 (no resizes) -----
    {
        int g = 32, K = 588, Kp = 592, c = 1024;
        int ptotal = BATCH * g * g * Kp;
        patchify_kernel<<<(ptotal + T - 1) / T, T>>>(x, 448, 14, g, K, Kp);
        tf32_gemm_kernel<<<dim3(c / 128, BATCH * g * g / 128), 256>>>(
            p_patches, Kp, wt[0], c, K, bt[0], p_feat, c, nullptr, 0);
        tf32_gemm_kernel<<<dim3(HID / 128, BATCH * TOK / 128), 256>>>(
            p_feat, c, wp[0], HID, c, bp[0], out, HID, p_wi + 0 * BATCH, 0);
    }

    // ---------------- Expert 1: s=336, p=14, g=24, c=768 -------------------
    {
        int g = 24, K = 588, Kp = 592, c = 768;
        int rtotal = BATCH * 3 * 336 * 336;
        resize_img_kernel<<<(rtotal + T - 1) / T, T>>>(x);
        int ptotal = BATCH * g * g * Kp;
        patchify_kernel<<<(ptotal + T - 1) / T, T>>>(p_x336, 336, 14, g, K, Kp);
        tf32_gemm_kernel<<<dim3(c / 128, BATCH * g * g / 128), 256>>>(
            p_patches, Kp, wt[1], c, K, bt[1], p_feat, c, nullptr, 0);
        int ftotal = BATCH * TOK * c;
        resize_feat_kernel<<<(ftotal + T - 1) / T, T>>>(g, c);
        tf32_gemm_kernel<<<dim3(HID / 128, BATCH * TOK / 128), 256>>>(
            p_feat2, c, wp[1], HID, c, bp[1], out, HID, p_wi + 1 * BATCH, 1);
    }

    // ---------------- Expert 2: s=448, p=32, g=14, c=1152 ------------------
    {
        int g = 14, K = 3072, c = 1152;
        int ptotal = BATCH * g * g * K;
        patchify_kernel<<<(ptotal + T - 1) / T, T>>>(x, 448, 32, g, K, K);
        tf32_gemm_kernel<<<dim3(c / 128, BATCH * g * g / 128), 256>>>(
            p_patches, K, wt[2], c, K, bt[2], p_feat, c, nullptr, 0);
        int ftotal = BATCH * TOK * c;
        resize_feat_kernel<<<(ftotal + T - 1) / T, T>>>(g, c);
        tf32_gemm_kernel<<<dim3(HID / 128, BATCH * TOK / 128), 256>>>(
            p_feat2, c, wp[2], HID, c, bp[2], out, HID, p_wi + 2 * BATCH, 1);
    }
}